// round 3
// baseline (speedup 1.0000x reference)
#include <cuda_runtime.h>
#include <cstddef>

#define S_LEN  2048
#define NB     4
#define NH     8
#define DKH    64
#define DMODEL 512
#define MROWS  (NB * S_LEN)        // 8192

// ---- scratch (device globals: allocation-free rule) ----
__device__ float g_Qp[NB * NH * S_LEN * DKH];   // [B,H,S,dk] 16 MB
__device__ float g_Kp[NB * NH * S_LEN * DKH];
__device__ float g_Vp[NB * NH * S_LEN * DKH];
__device__ float g_ctx[NB * S_LEN * DMODEL];    // [B,S,D]

// ============================================================
// C[i,j] = sum_k A[i,k] * W[j,k]   (y = x @ W^T)
// A: [M=8192, 512] row-major, W: [512, 512] row-major.
// 128x128 tile, BK=8, 256 threads, 8x8 microtile.
// PERMUTE: write C as [B,H,S,dk] instead of [M,512].
// ============================================================
template <bool PERMUTE>
__global__ void __launch_bounds__(256) gemm_xwt_kernel(
    const float* __restrict__ A, const float* __restrict__ W,
    float* __restrict__ C)
{
    __shared__ float As[8][128];
    __shared__ float Bs[8][128];

    const int tid = threadIdx.x;
    const int tx = tid & 15;
    const int ty = tid >> 4;
    const int rowBase = blockIdx.y * 128;
    const int colBase = blockIdx.x * 128;

    const int lr = tid >> 1;          // 0..127
    const int lk = (tid & 1) * 4;     // 0 or 4

    const float* Aptr = A + (size_t)(rowBase + lr) * DMODEL + lk;
    const float* Wptr = W + (size_t)(colBase + lr) * DMODEL + lk;

    float acc[8][8];
#pragma unroll
    for (int u = 0; u < 8; u++)
#pragma unroll
        for (int v = 0; v < 8; v++) acc[u][v] = 0.0f;

    for (int k0 = 0; k0 < DMODEL; k0 += 8) {
        float4 a4 = *(const float4*)(Aptr + k0);
        float4 b4 = *(const float4*)(Wptr + k0);
        As[lk + 0][lr] = a4.x; As[lk + 1][lr] = a4.y;
        As[lk + 2][lr] = a4.z; As[lk + 3][lr] = a4.w;
        Bs[lk + 0][lr] = b4.x; Bs[lk + 1][lr] = b4.y;
        Bs[lk + 2][lr] = b4.z; Bs[lk + 3][lr] = b4.w;
        __syncthreads();
#pragma unroll
        for (int k = 0; k < 8; k++) {
            float a[8], b[8];
            *(float4*)&a[0] = *(const float4*)&As[k][ty * 8];
            *(float4*)&a[4] = *(const float4*)&As[k][ty * 8 + 4];
            *(float4*)&b[0] = *(const float4*)&Bs[k][tx * 8];
            *(float4*)&b[4] = *(const float4*)&Bs[k][tx * 8 + 4];
#pragma unroll
            for (int u = 0; u < 8; u++)
#pragma unroll
                for (int v = 0; v < 8; v++)
                    acc[u][v] += a[u] * b[v];
        }
        __syncthreads();
    }

#pragma unroll
    for (int u = 0; u < 8; u++) {
        const int i = rowBase + ty * 8 + u;
#pragma unroll
        for (int v = 0; v < 8; v++) {
            const int j = colBase + tx * 8 + v;
            if (PERMUTE) {
                const int b = i >> 11;          // i / 2048
                const int s = i & 2047;
                const int h = j >> 6;           // j / 64
                const int jj = j & 63;
                C[(((size_t)(b * NH + h) * S_LEN) + s) * DKH + jj] = acc[u][v];
            } else {
                C[(size_t)i * DMODEL + j] = acc[u][v];
            }
        }
    }
}

// ============================================================
// Causal flash attention.
// grid = (S/64 qtiles, B*H), block = 256 (16x16 logical),
// each thread owns a 4x4 score/output microtile.
// smem: qs[64][65] (pre-scaled Q), ks[64][65] (K tile, reused as P),
//       vs[64][65].  49,920 B dynamic.
// ============================================================
#define ATTN_SMEM (3 * 64 * 65 * 4)

__global__ void __launch_bounds__(256) attn_kernel(
    const float* __restrict__ Qp, const float* __restrict__ Kp,
    const float* __restrict__ Vp, float* __restrict__ ctx)
{
    extern __shared__ float sm[];
    float* qs = sm;                  // stride 65
    float* ks = sm + 64 * 65;        // stride 65 (reused as P)
    float* vs = sm + 2 * 64 * 65;    // stride 65

    const int tid = threadIdx.x;
    const int tx = tid & 15;
    const int ty = tid >> 4;
    const int bh = blockIdx.y;       // 0..31
    const int qt = blockIdx.x;       // 0..31

    const size_t base = (size_t)bh * S_LEN * DKH;
    const float* Qb = Qp + base + (size_t)qt * 64 * DKH;
    const float* Kb = Kp + base;
    const float* Vb = Vp + base;

    // load Q tile, pre-scaled by 1/sqrt(dk) = 0.125
    for (int e = tid; e < 64 * 16; e += 256) {
        const int r = e >> 4;
        const int c4 = (e & 15) * 4;
        float4 v = *(const float4*)&Qb[r * DKH + c4];
        qs[r * 65 + c4 + 0] = v.x * 0.125f;
        qs[r * 65 + c4 + 1] = v.y * 0.125f;
        qs[r * 65 + c4 + 2] = v.z * 0.125f;
        qs[r * 65 + c4 + 3] = v.w * 0.125f;
    }

    float m[4], l[4], acc[4][4];
#pragma unroll
    for (int i = 0; i < 4; i++) {
        m[i] = -1e30f; l[i] = 0.0f;
#pragma unroll
        for (int j = 0; j < 4; j++) acc[i][j] = 0.0f;
    }

    for (int kt = 0; kt <= qt; kt++) {
        __syncthreads();   // prev-iter readers of ks/vs done (and Q visible on iter 0)
        for (int e = tid; e < 64 * 16; e += 256) {
            const int r = e >> 4;
            const int c4 = (e & 15) * 4;
            float4 kv = *(const float4*)&Kb[(size_t)(kt * 64 + r) * DKH + c4];
            float4 vv = *(const float4*)&Vb[(size_t)(kt * 64 + r) * DKH + c4];
            ks[r * 65 + c4 + 0] = kv.x; ks[r * 65 + c4 + 1] = kv.y;
            ks[r * 65 + c4 + 2] = kv.z; ks[r * 65 + c4 + 3] = kv.w;
            vs[r * 65 + c4 + 0] = vv.x; vs[r * 65 + c4 + 1] = vv.y;
            vs[r * 65 + c4 + 2] = vv.z; vs[r * 65 + c4 + 3] = vv.w;
        }
        __syncthreads();

        // S = Qs @ K^T  (scores already scaled via Q)
        float s[4][4];
#pragma unroll
        for (int i = 0; i < 4; i++)
#pragma unroll
            for (int j = 0; j < 4; j++) s[i][j] = 0.0f;

#pragma unroll 8
        for (int k = 0; k < 64; k++) {
            float qa[4], kb[4];
#pragma unroll
            for (int i = 0; i < 4; i++) qa[i] = qs[(4 * ty + i) * 65 + k];
#pragma unroll
            for (int j = 0; j < 4; j++) kb[j] = ks[(4 * tx + j) * 65 + k];
#pragma unroll
            for (int i = 0; i < 4; i++)
#pragma unroll
                for (int j = 0; j < 4; j++)
                    s[i][j] += qa[i] * kb[j];
        }

        if (kt == qt) {
            // diagonal tile: mask cols > rows
#pragma unroll
            for (int i = 0; i < 4; i++)
#pragma unroll
                for (int j = 0; j < 4; j++)
                    if ((4 * tx + j) > (4 * ty + i)) s[i][j] = -1e30f;
        }

        // online softmax update (16-lane row groups; xor masks 1,2,4,8
        // stay inside each half-warp = one ty group)
#pragma unroll
        for (int i = 0; i < 4; i++) {
            float mx = fmaxf(fmaxf(s[i][0], s[i][1]), fmaxf(s[i][2], s[i][3]));
            mx = fmaxf(mx, __shfl_xor_sync(0xffffffffu, mx, 1));
            mx = fmaxf(mx, __shfl_xor_sync(0xffffffffu, mx, 2));
            mx = fmaxf(mx, __shfl_xor_sync(0xffffffffu, mx, 4));
            mx = fmaxf(mx, __shfl_xor_sync(0xffffffffu, mx, 8));
            const float mn = fmaxf(m[i], mx);
            const float al = __expf(m[i] - mn);
            m[i] = mn;
            float rs = 0.0f;
#pragma unroll
            for (int j = 0; j < 4; j++) {
                s[i][j] = __expf(s[i][j] - mn);
                rs += s[i][j];
            }
            rs += __shfl_xor_sync(0xffffffffu, rs, 1);
            rs += __shfl_xor_sync(0xffffffffu, rs, 2);
            rs += __shfl_xor_sync(0xffffffffu, rs, 4);
            rs += __shfl_xor_sync(0xffffffffu, rs, 8);
            l[i] = l[i] * al + rs;
#pragma unroll
            for (int j = 0; j < 4; j++) acc[i][j] *= al;
        }

        __syncthreads();   // all score-readers of ks done before P overwrites it
#pragma unroll
        for (int i = 0; i < 4; i++)
#pragma unroll
            for (int j = 0; j < 4; j++)
                ks[(4 * ty + i) * 65 + 4 * tx + j] = s[i][j];
        __syncwarp();      // P rows are produced & consumed within one half-warp group

        // O += P @ V
#pragma unroll 8
        for (int k = 0; k < 64; k++) {
            float pa[4], vb[4];
#pragma unroll
            for (int i = 0; i < 4; i++) pa[i] = ks[(4 * ty + i) * 65 + k];
#pragma unroll
            for (int j = 0; j < 4; j++) vb[j] = vs[k * 65 + 4 * tx + j];
#pragma unroll
            for (int i = 0; i < 4; i++)
#pragma unroll
                for (int j = 0; j < 4; j++)
                    acc[i][j] += pa[i] * vb[j];
        }
    }

    // epilogue: ctx[b, s, h*64 + c] = acc / l
    const int b = bh >> 3;
    const int h = bh & 7;
#pragma unroll
    for (int i = 0; i < 4; i++) {
        const float inv = 1.0f / l[i];
        const int srow = qt * 64 + 4 * ty + i;
        float4 o;
        o.x = acc[i][0] * inv;
        o.y = acc[i][1] * inv;
        o.z = acc[i][2] * inv;
        o.w = acc[i][3] * inv;
        *(float4*)&ctx[((size_t)b * S_LEN + srow) * DMODEL + h * DKH + 4 * tx] = o;
    }
}

// ============================================================
extern "C" void kernel_launch(void* const* d_in, const int* in_sizes, int n_in,
                              void* d_out, int out_size)
{
    const float* iQ = (const float*)d_in[0];
    const float* iK = (const float*)d_in[1];
    const float* iV = (const float*)d_in[2];
    const float* WQ = (const float*)d_in[3];
    const float* WK = (const float*)d_in[4];
    const float* WV = (const float*)d_in[5];
    const float* WO = (const float*)d_in[6];

    float *Qp, *Kp, *Vp, *Ctx;
    cudaGetSymbolAddress((void**)&Qp, g_Qp);
    cudaGetSymbolAddress((void**)&Kp, g_Kp);
    cudaGetSymbolAddress((void**)&Vp, g_Vp);
    cudaGetSymbolAddress((void**)&Ctx, g_ctx);

    cudaFuncSetAttribute(attn_kernel,
                         cudaFuncAttributeMaxDynamicSharedMemorySize, ATTN_SMEM);

    const dim3 ggrid(DMODEL / 128, MROWS / 128);   // (4, 64)
    gemm_xwt_kernel<true><<<ggrid, 256>>>(iQ, WQ, Qp);
    gemm_xwt_kernel<true><<<ggrid, 256>>>(iK, WK, Kp);
    gemm_xwt_kernel<true><<<ggrid, 256>>>(iV, WV, Vp);

    attn_kernel<<<dim3(S_LEN / 64, NB * NH), 256, ATTN_SMEM>>>(Qp, Kp, Vp, Ctx);

    gemm_xwt_kernel<false><<<ggrid, 256>>>(Ctx, WO, (float*)d_out);
}

// round 5
// speedup vs baseline: 1.0031x; 1.0031x over previous
#include <cuda_runtime.h>
#include <cstddef>

#define S_LEN  2048
#define NB     4
#define NH     8
#define DKH    64
#define DMODEL 512
#define MROWS  (NB * S_LEN)        // 8192

// ---- scratch (device globals: allocation-free rule) ----
__device__ float g_Qp[NB * NH * S_LEN * DKH];   // [B,H,S,dk] 16 MB
__device__ float g_Kp[NB * NH * S_LEN * DKH];
__device__ float g_Vp[NB * NH * S_LEN * DKH];
__device__ float g_ctx[NB * S_LEN * DMODEL];    // [B,S,D]

// ============================================================
// C[i,j] = sum_k A[i,k] * W[j,k]   (y = x @ W^T)
// A: [M=8192, 512] row-major, W: [512, 512] row-major.
// 128x128 tile, BK=8, 256 threads, 8x8 microtile.
// PERMUTE: write C as [B,H,S,dk] instead of [M,512].
// ============================================================
template <bool PERMUTE>
__global__ void __launch_bounds__(256) gemm_xwt_kernel(
    const float* __restrict__ A, const float* __restrict__ W,
    float* __restrict__ C)
{
    __shared__ float As[8][128];
    __shared__ float Bs[8][128];

    const int tid = threadIdx.x;
    const int tx = tid & 15;
    const int ty = tid >> 4;
    const int rowBase = blockIdx.y * 128;
    const int colBase = blockIdx.x * 128;

    const int lr = tid >> 1;          // 0..127
    const int lk = (tid & 1) * 4;     // 0 or 4

    const float* Aptr = A + (size_t)(rowBase + lr) * DMODEL + lk;
    const float* Wptr = W + (size_t)(colBase + lr) * DMODEL + lk;

    float acc[8][8];
#pragma unroll
    for (int u = 0; u < 8; u++)
#pragma unroll
        for (int v = 0; v < 8; v++) acc[u][v] = 0.0f;

    for (int k0 = 0; k0 < DMODEL; k0 += 8) {
        float4 a4 = *(const float4*)(Aptr + k0);
        float4 b4 = *(const float4*)(Wptr + k0);
        As[lk + 0][lr] = a4.x; As[lk + 1][lr] = a4.y;
        As[lk + 2][lr] = a4.z; As[lk + 3][lr] = a4.w;
        Bs[lk + 0][lr] = b4.x; Bs[lk + 1][lr] = b4.y;
        Bs[lk + 2][lr] = b4.z; Bs[lk + 3][lr] = b4.w;
        __syncthreads();
#pragma unroll
        for (int k = 0; k < 8; k++) {
            float a[8], b[8];
            *(float4*)&a[0] = *(const float4*)&As[k][ty * 8];
            *(float4*)&a[4] = *(const float4*)&As[k][ty * 8 + 4];
            *(float4*)&b[0] = *(const float4*)&Bs[k][tx * 8];
            *(float4*)&b[4] = *(const float4*)&Bs[k][tx * 8 + 4];
#pragma unroll
            for (int u = 0; u < 8; u++)
#pragma unroll
                for (int v = 0; v < 8; v++)
                    acc[u][v] += a[u] * b[v];
        }
        __syncthreads();
    }

#pragma unroll
    for (int u = 0; u < 8; u++) {
        const int i = rowBase + ty * 8 + u;
#pragma unroll
        for (int v = 0; v < 8; v++) {
            const int j = colBase + tx * 8 + v;
            if (PERMUTE) {
                const int b = i >> 11;          // i / 2048
                const int s = i & 2047;
                const int h = j >> 6;           // j / 64
                const int jj = j & 63;
                C[(((size_t)(b * NH + h) * S_LEN) + s) * DKH + jj] = acc[u][v];
            } else {
                C[(size_t)i * DMODEL + j] = acc[u][v];
            }
        }
    }
}

// ============================================================
// Causal flash attention.
// grid = (S/64 qtiles, B*H), block = 256 (16x16 logical),
// each thread owns a 4x4 score/output microtile.
// smem: qs[64][65] (pre-scaled Q), ks[64][65] (K tile, reused as P),
//       vs[64][65].  49,920 B dynamic.
// ============================================================
#define ATTN_SMEM (3 * 64 * 65 * 4)

__global__ void __launch_bounds__(256) attn_kernel(
    const float* __restrict__ Qp, const float* __restrict__ Kp,
    const float* __restrict__ Vp, float* __restrict__ ctx)
{
    extern __shared__ float sm[];
    float* qs = sm;                  // stride 65
    float* ks = sm + 64 * 65;        // stride 65 (reused as P)
    float* vs = sm + 2 * 64 * 65;    // stride 65

    const int tid = threadIdx.x;
    const int tx = tid & 15;
    const int ty = tid >> 4;
    const int bh = blockIdx.y;       // 0..31
    const int qt = blockIdx.x;       // 0..31

    const size_t base = (size_t)bh * S_LEN * DKH;
    const float* Qb = Qp + base + (size_t)qt * 64 * DKH;
    const float* Kb = Kp + base;
    const float* Vb = Vp + base;

    // load Q tile, pre-scaled by 1/sqrt(dk) = 0.125
    for (int e = tid; e < 64 * 16; e += 256) {
        const int r = e >> 4;
        const int c4 = (e & 15) * 4;
        float4 v = *(const float4*)&Qb[r * DKH + c4];
        qs[r * 65 + c4 + 0] = v.x * 0.125f;
        qs[r * 65 + c4 + 1] = v.y * 0.125f;
        qs[r * 65 + c4 + 2] = v.z * 0.125f;
        qs[r * 65 + c4 + 3] = v.w * 0.125f;
    }

    float m[4], l[4], acc[4][4];
#pragma unroll
    for (int i = 0; i < 4; i++) {
        m[i] = -1e30f; l[i] = 0.0f;
#pragma unroll
        for (int j = 0; j < 4; j++) acc[i][j] = 0.0f;
    }

    for (int kt = 0; kt <= qt; kt++) {
        __syncthreads();   // prev-iter readers of ks/vs done (and Q visible on iter 0)
        for (int e = tid; e < 64 * 16; e += 256) {
            const int r = e >> 4;
            const int c4 = (e & 15) * 4;
            float4 kv = *(const float4*)&Kb[(size_t)(kt * 64 + r) * DKH + c4];
            float4 vv = *(const float4*)&Vb[(size_t)(kt * 64 + r) * DKH + c4];
            ks[r * 65 + c4 + 0] = kv.x; ks[r * 65 + c4 + 1] = kv.y;
            ks[r * 65 + c4 + 2] = kv.z; ks[r * 65 + c4 + 3] = kv.w;
            vs[r * 65 + c4 + 0] = vv.x; vs[r * 65 + c4 + 1] = vv.y;
            vs[r * 65 + c4 + 2] = vv.z; vs[r * 65 + c4 + 3] = vv.w;
        }
        __syncthreads();

        // S = Qs @ K^T  (scores already scaled via Q)
        float s[4][4];
#pragma unroll
        for (int i = 0; i < 4; i++)
#pragma unroll
            for (int j = 0; j < 4; j++) s[i][j] = 0.0f;

#pragma unroll 8
        for (int k = 0; k < 64; k++) {
            float qa[4], kb[4];
#pragma unroll
            for (int i = 0; i < 4; i++) qa[i] = qs[(4 * ty + i) * 65 + k];
#pragma unroll
            for (int j = 0; j < 4; j++) kb[j] = ks[(4 * tx + j) * 65 + k];
#pragma unroll
            for (int i = 0; i < 4; i++)
#pragma unroll
                for (int j = 0; j < 4; j++)
                    s[i][j] += qa[i] * kb[j];
        }

        if (kt == qt) {
            // diagonal tile: mask cols > rows
#pragma unroll
            for (int i = 0; i < 4; i++)
#pragma unroll
                for (int j = 0; j < 4; j++)
                    if ((4 * tx + j) > (4 * ty + i)) s[i][j] = -1e30f;
        }

        // online softmax update (16-lane row groups; xor masks 1,2,4,8
        // stay inside each half-warp = one ty group)
#pragma unroll
        for (int i = 0; i < 4; i++) {
            float mx = fmaxf(fmaxf(s[i][0], s[i][1]), fmaxf(s[i][2], s[i][3]));
            mx = fmaxf(mx, __shfl_xor_sync(0xffffffffu, mx, 1));
            mx = fmaxf(mx, __shfl_xor_sync(0xffffffffu, mx, 2));
            mx = fmaxf(mx, __shfl_xor_sync(0xffffffffu, mx, 4));
            mx = fmaxf(mx, __shfl_xor_sync(0xffffffffu, mx, 8));
            const float mn = fmaxf(m[i], mx);
            const float al = __expf(m[i] - mn);
            m[i] = mn;
            float rs = 0.0f;
#pragma unroll
            for (int j = 0; j < 4; j++) {
                s[i][j] = __expf(s[i][j] - mn);
                rs += s[i][j];
            }
            rs += __shfl_xor_sync(0xffffffffu, rs, 1);
            rs += __shfl_xor_sync(0xffffffffu, rs, 2);
            rs += __shfl_xor_sync(0xffffffffu, rs, 4);
            rs += __shfl_xor_sync(0xffffffffu, rs, 8);
            l[i] = l[i] * al + rs;
#pragma unroll
            for (int j = 0; j < 4; j++) acc[i][j] *= al;
        }

        __syncthreads();   // all score-readers of ks done before P overwrites it
#pragma unroll
        for (int i = 0; i < 4; i++)
#pragma unroll
            for (int j = 0; j < 4; j++)
                ks[(4 * ty + i) * 65 + 4 * tx + j] = s[i][j];
        __syncwarp();      // P rows are produced & consumed within one half-warp group

        // O += P @ V
#pragma unroll 8
        for (int k = 0; k < 64; k++) {
            float pa[4], vb[4];
#pragma unroll
            for (int i = 0; i < 4; i++) pa[i] = ks[(4 * ty + i) * 65 + k];
#pragma unroll
            for (int j = 0; j < 4; j++) vb[j] = vs[k * 65 + 4 * tx + j];
#pragma unroll
            for (int i = 0; i < 4; i++)
#pragma unroll
                for (int j = 0; j < 4; j++)
                    acc[i][j] += pa[i] * vb[j];
        }
    }

    // epilogue: ctx[b, s, h*64 + c] = acc / l
    const int b = bh >> 3;
    const int h = bh & 7;
#pragma unroll
    for (int i = 0; i < 4; i++) {
        const float inv = 1.0f / l[i];
        const int srow = qt * 64 + 4 * ty + i;
        float4 o;
        o.x = acc[i][0] * inv;
        o.y = acc[i][1] * inv;
        o.z = acc[i][2] * inv;
        o.w = acc[i][3] * inv;
        *(float4*)&ctx[((size_t)b * S_LEN + srow) * DMODEL + h * DKH + 4 * tx] = o;
    }
}

// ============================================================
extern "C" void kernel_launch(void* const* d_in, const int* in_sizes, int n_in,
                              void* d_out, int out_size)
{
    const float* iQ = (const float*)d_in[0];
    const float* iK = (const float*)d_in[1];
    const float* iV = (const float*)d_in[2];
    const float* WQ = (const float*)d_in[3];
    const float* WK = (const float*)d_in[4];
    const float* WV = (const float*)d_in[5];
    const float* WO = (const float*)d_in[6];

    float *Qp, *Kp, *Vp, *Ctx;
    cudaGetSymbolAddress((void**)&Qp, g_Qp);
    cudaGetSymbolAddress((void**)&Kp, g_Kp);
    cudaGetSymbolAddress((void**)&Vp, g_Vp);
    cudaGetSymbolAddress((void**)&Ctx, g_ctx);

    cudaFuncSetAttribute(attn_kernel,
                         cudaFuncAttributeMaxDynamicSharedMemorySize, ATTN_SMEM);

    const dim3 ggrid(DMODEL / 128, MROWS / 128);   // (4, 64)
    gemm_xwt_kernel<true><<<ggrid, 256>>>(iQ, WQ, Qp);
    gemm_xwt_kernel<true><<<ggrid, 256>>>(iK, WK, Kp);
    gemm_xwt_kernel<true><<<ggrid, 256>>>(iV, WV, Vp);

    attn_kernel<<<dim3(S_LEN / 64, NB * NH), 256, ATTN_SMEM>>>(Qp, Kp, Vp, Ctx);

    gemm_xwt_kernel<false><<<ggrid, 256>>>(Ctx, WO, (float*)d_out);
}